// round 4
// baseline (speedup 1.0000x reference)
#include <cuda_runtime.h>

// GHMRankingLoss, fully fused single kernel:
//   result = (1/N) * sum_b max(count_b,1)^-0.75 * sum_{i in bin b} loss_i
//
// - One pass over the 3 fp32 arrays (201 MB), grid-stride, unroll-2 float4.
// - Per-lane private smem histogram for LOSS only (float, conflict-free).
//   COUNTS live in 2 packed u32 registers (6 bits/bin, <=55 elems/thread).
// - MUFU-free binning: floor(10*sigmoid(x)) via 4 symmetric logit thresholds.
// - 8 CTAs/SM full wave (NB=1184), __launch_bounds__(256,8).
// - Last block (threadfence+ticket) reduces partials from L2 in double,
//   applies w_b = max(c,1)^-0.75, writes the scalar mean, resets the ticket.

#define BINS 10
#define NT 256
#define NB 1184   // 8 CTAs/SM * 148 SMs = one full wave, 64 warps/SM

__device__ float2 g_part[BINS * NB];   // bin-major: [bin][block] (loss_sum, count)
__device__ unsigned int g_ticket;      // zero at load; last block resets

// bin = clip(floor(10*sigmoid(x)), 0, 9):  sigmoid(x) >= k/10 <=> x >= ln(k/(10-k))
__device__ __forceinline__ int ghm_bin(float x) {
    float ax = fabsf(x);
    int m = 0;
    m += (ax >= 0.40546511f);   // ln(6/4)
    m += (ax >= 0.84729786f);   // ln(7/3)
    m += (ax >= 1.38629436f);   // ln(8/2)
    m += (ax >= 2.19722458f);   // ln(9/1)
    return (x >= 0.0f) ? (5 + m) : (4 - m);
}

__device__ __forceinline__ void ghm_accum(float* __restrict__ h,
                                          unsigned int& cnt_lo, unsigned int& cnt_hi,
                                          float o1, float o2, float t) {
    float diff = o1 - o2;
    float loss = fmaxf(0.0f, -t * diff);      // margin = 0
    float es   = fmaf(2.0f, t, -1.0f);        // expected_sign = 2t-1 (t=+-1 -> {1,-3})
    float x    = -diff * es;
    int bi = ghm_bin(x);
    // loss sum: per-lane private smem slot (stride NT floats -> conflict-free)
    h[bi * NT] += loss;
    // count: packed 6-bit fields, bins 0-4 in lo, 5-9 in hi
    bool hi5 = bi >= 5;
    unsigned int inc = 1u << (6 * (hi5 ? bi - 5 : bi));
    if (hi5) cnt_hi += inc; else cnt_lo += inc;
}

__global__ void __launch_bounds__(NT, 8)
ghm_fused_k(const float* __restrict__ o1,
            const float* __restrict__ o2,
            const float* __restrict__ tg,
            float* __restrict__ out,
            int n) {
    __shared__ float hist[BINS * NT];           // loss sums
    __shared__ float csum[BINS * NT];           // unpacked counts (reused post-loop)
    const int tid = threadIdx.x;
    const int bid = blockIdx.x;

    #pragma unroll
    for (int b = 0; b < BINS; b++)
        hist[b * NT + tid] = 0.0f;
    __syncthreads();

    float* h = &hist[tid];
    unsigned int cnt_lo = 0u, cnt_hi = 0u;

    const int n4     = n >> 2;
    const int stride = NB * NT;
    int i = bid * NT + tid;

    const float4* __restrict__ A = (const float4*)o1;
    const float4* __restrict__ B = (const float4*)o2;
    const float4* __restrict__ T = (const float4*)tg;

    // unroll-2: 6 front-batched LDG.128 per iteration
    for (; i + stride < n4; i += 2 * stride) {
        float4 a0 = __ldcs(A + i);
        float4 b0 = __ldcs(B + i);
        float4 t0 = __ldcs(T + i);
        float4 a1 = __ldcs(A + i + stride);
        float4 b1 = __ldcs(B + i + stride);
        float4 t1 = __ldcs(T + i + stride);
        ghm_accum(h, cnt_lo, cnt_hi, a0.x, b0.x, t0.x);
        ghm_accum(h, cnt_lo, cnt_hi, a0.y, b0.y, t0.y);
        ghm_accum(h, cnt_lo, cnt_hi, a0.z, b0.z, t0.z);
        ghm_accum(h, cnt_lo, cnt_hi, a0.w, b0.w, t0.w);
        ghm_accum(h, cnt_lo, cnt_hi, a1.x, b1.x, t1.x);
        ghm_accum(h, cnt_lo, cnt_hi, a1.y, b1.y, t1.y);
        ghm_accum(h, cnt_lo, cnt_hi, a1.z, b1.z, t1.z);
        ghm_accum(h, cnt_lo, cnt_hi, a1.w, b1.w, t1.w);
    }
    for (; i < n4; i += stride) {
        float4 a = __ldcs(A + i);
        float4 b = __ldcs(B + i);
        float4 t = __ldcs(T + i);
        ghm_accum(h, cnt_lo, cnt_hi, a.x, b.x, t.x);
        ghm_accum(h, cnt_lo, cnt_hi, a.y, b.y, t.y);
        ghm_accum(h, cnt_lo, cnt_hi, a.z, b.z, t.z);
        ghm_accum(h, cnt_lo, cnt_hi, a.w, b.w, t.w);
    }
    for (int j = (n4 << 2) + bid * NT + tid; j < n; j += stride)
        ghm_accum(h, cnt_lo, cnt_hi, o1[j], o2[j], tg[j]);

    // unpack counts into smem (per-lane slots, conflict-free)
    #pragma unroll
    for (int b = 0; b < 5; b++) {
        csum[b * NT + tid]       = (float)((cnt_lo >> (6 * b)) & 63u);
        csum[(b + 5) * NT + tid] = (float)((cnt_hi >> (6 * b)) & 63u);
    }
    __syncthreads();

    // tree-reduce 256 lanes for all 10 bins (loss + count)
    #pragma unroll
    for (int s = NT / 2; s >= 1; s >>= 1) {
        if (tid < s) {
            #pragma unroll
            for (int b = 0; b < BINS; b++) {
                hist[b * NT + tid] += hist[b * NT + tid + s];
                csum[b * NT + tid] += csum[b * NT + tid + s];
            }
        }
        __syncthreads();
    }

    // publish this block's 10 partials (bin-major), then grab a ticket
    if (tid < BINS)
        g_part[tid * NB + bid] = make_float2(hist[tid * NT], csum[tid * NT]);

    __shared__ bool isLast;
    __threadfence();
    if (tid == 0) {
        unsigned int v = atomicAdd(&g_ticket, 1u);
        isLast = (v == NB - 1);
    }
    __syncthreads();
    if (!isLast) return;

    // ---- last block: reduce NB partials per bin (L2-resident), finalize ----
    const int warp = tid >> 5;
    const int lane = tid & 31;
    __shared__ double ss[BINS], cc[BINS];

    for (int b = warp; b < BINS; b += NT / 32) {
        double s = 0.0, c = 0.0;
        for (int k = lane; k < NB; k += 32) {
            float2 p = g_part[b * NB + k];
            s += (double)p.x;
            c += (double)p.y;
        }
        #pragma unroll
        for (int off = 16; off; off >>= 1) {
            s += __shfl_down_sync(0xffffffff, s, off);
            c += __shfl_down_sync(0xffffffff, c, off);
        }
        if (lane == 0) { ss[b] = s; cc[b] = c; }
    }
    __syncthreads();

    if (tid == 0) {
        double acc = 0.0;
        #pragma unroll
        for (int b = 0; b < BINS; b++) {
            double tot = cc[b] < 1.0 ? 1.0 : cc[b];   // clamp(min=1)
            acc += pow(tot, -0.75) * ss[b];           // w = tot^-alpha
        }
        out[0] = (float)(acc / (double)n);
        g_ticket = 0;                                  // reset for graph replay
    }
}

extern "C" void kernel_launch(void* const* d_in, const int* in_sizes, int n_in,
                              void* d_out, int out_size) {
    const float* o1 = (const float*)d_in[0];
    const float* o2 = (const float*)d_in[1];
    const float* tg = (const float*)d_in[2];
    float* out = (float*)d_out;
    int n = in_sizes[0];

    ghm_fused_k<<<NB, NT>>>(o1, o2, tg, out, n);
}

// round 5
// speedup vs baseline: 1.4023x; 1.4023x over previous
#include <cuda_runtime.h>

// GHMRankingLoss, fused single kernel, histogram-free hot loop.
//
// Math: result = (1/N) * sum_{b=5..9} max(cnt_b,1)^-0.75 * S_b   because
// loss>0 <=> x>0 <=> bin>=5, so bins 0-4 contribute w_b * 0 = 0.
// With u = -t*diff (== loss when u>=0) and x = u*(2-t) (the sigmoid arg),
// bin 5+m passes exactly the thresholds T_0..T_m where
//   T = {0, ln(6/4), ln(7/3), ln(8/2), ln(9/1)}  (sigmoid(x)>=k/10 <=> x>=ln(k/(10-k)))
// Keep cumulative register tallies C_k = sum_{x>=T_k} u, N_k = #{x>=T_k};
// then S_{5+m} = C_m - C_{m+1}, cnt_{5+m} = N_m - N_{m+1}. No smem RMW,
// no dynamic indexing -> no serialized memory chains in the loop.
//
// Last block (threadfence + ticket) reduces the per-block partials from L2
// in double, differences them, applies w = max(cnt,1)^-0.75, writes the mean.

#define NT 256
#define NB 1184   // 148 SMs * 8; grid-stride so residency doesn't matter
#define K  5

__device__ float2 g_part[K * NB];   // k-major: [k][block] = (C_k, N_k)
__device__ unsigned int g_ticket;   // zero at load; last block resets

__device__ __forceinline__ void ghm_accum(
    float& c0, float& c1, float& c2, float& c3, float& c4,
    int& n0, int& n1, int& n2, int& n3, int& n4,
    float a, float b, float t) {
    float diff = a - b;
    float u = -t * diff;            // == loss whenever u >= 0
    float x = u * (2.0f - t);       // sigmoid argument (t=+1 -> u, t=-1 -> 3u)
    bool p0 = (x >= 0.0f);
    bool p1 = (x >= 0.40546511f);   // ln(6/4)
    bool p2 = (x >= 0.84729786f);   // ln(7/3)
    bool p3 = (x >= 1.38629436f);   // ln(8/2)
    bool p4 = (x >= 2.19722458f);   // ln(9/1)
    c0 += p0 ? u : 0.0f;  n0 += p0;
    c1 += p1 ? u : 0.0f;  n1 += p1;
    c2 += p2 ? u : 0.0f;  n2 += p2;
    c3 += p3 ? u : 0.0f;  n3 += p3;
    c4 += p4 ? u : 0.0f;  n4 += p4;
}

#define ACC(av, bv, tv) ghm_accum(c0,c1,c2,c3,c4,n0,n1,n2,n3,n4, av, bv, tv)

__global__ void __launch_bounds__(NT)
ghm_fused_k(const float* __restrict__ o1,
            const float* __restrict__ o2,
            const float* __restrict__ tg,
            float* __restrict__ out,
            int n) {
    const int tid = threadIdx.x;
    const int bid = blockIdx.x;

    float c0 = 0.f, c1 = 0.f, c2 = 0.f, c3 = 0.f, c4 = 0.f;
    int   n0 = 0,   n1 = 0,   n2 = 0,   n3 = 0,   n4 = 0;

    const int n4e    = n >> 2;
    const int stride = NB * NT;
    int i = bid * NT + tid;

    const float4* __restrict__ A = (const float4*)o1;
    const float4* __restrict__ B = (const float4*)o2;
    const float4* __restrict__ T = (const float4*)tg;

    // unroll-2: 6 front-batched LDG.128 per iteration for MLP
    for (; i + stride < n4e; i += 2 * stride) {
        float4 a0 = __ldcs(A + i);
        float4 b0 = __ldcs(B + i);
        float4 t0 = __ldcs(T + i);
        float4 a1 = __ldcs(A + i + stride);
        float4 b1 = __ldcs(B + i + stride);
        float4 t1 = __ldcs(T + i + stride);
        ACC(a0.x, b0.x, t0.x);  ACC(a0.y, b0.y, t0.y);
        ACC(a0.z, b0.z, t0.z);  ACC(a0.w, b0.w, t0.w);
        ACC(a1.x, b1.x, t1.x);  ACC(a1.y, b1.y, t1.y);
        ACC(a1.z, b1.z, t1.z);  ACC(a1.w, b1.w, t1.w);
    }
    for (; i < n4e; i += stride) {
        float4 a = __ldcs(A + i);
        float4 b = __ldcs(B + i);
        float4 t = __ldcs(T + i);
        ACC(a.x, b.x, t.x);  ACC(a.y, b.y, t.y);
        ACC(a.z, b.z, t.z);  ACC(a.w, b.w, t.w);
    }
    for (int j = (n4e << 2) + bid * NT + tid; j < n; j += stride)
        ACC(o1[j], o2[j], tg[j]);

    // ---- block reduce: warp shfl, then cross-warp via smem ----
    float cs[K] = {c0, c1, c2, c3, c4};
    float ns[K] = {(float)n0, (float)n1, (float)n2, (float)n3, (float)n4};
    #pragma unroll
    for (int off = 16; off; off >>= 1) {
        #pragma unroll
        for (int k = 0; k < K; k++) {
            cs[k] += __shfl_down_sync(0xffffffff, cs[k], off);
            ns[k] += __shfl_down_sync(0xffffffff, ns[k], off);
        }
    }

    __shared__ float sC[K][NT / 32], sN[K][NT / 32];
    const int warp = tid >> 5, lane = tid & 31;
    if (lane == 0) {
        #pragma unroll
        for (int k = 0; k < K; k++) { sC[k][warp] = cs[k]; sN[k][warp] = ns[k]; }
    }
    __syncthreads();

    if (tid < K) {
        float c = 0.f, nn = 0.f;
        #pragma unroll
        for (int w = 0; w < NT / 32; w++) { c += sC[tid][w]; nn += sN[tid][w]; }
        g_part[tid * NB + bid] = make_float2(c, nn);
    }

    // ---- ticket: last block finalizes ----
    __shared__ bool isLast;
    __threadfence();
    if (tid == 0) {
        unsigned int v = atomicAdd(&g_ticket, 1u);
        isLast = (v == NB - 1);
    }
    __syncthreads();
    if (!isLast) return;

    __shared__ double ss[K], cc[K];
    if (warp < K) {
        double s = 0.0, c = 0.0;
        for (int j = lane; j < NB; j += 32) {
            float2 p = g_part[warp * NB + j];   // L2-resident
            s += (double)p.x;
            c += (double)p.y;
        }
        #pragma unroll
        for (int off = 16; off; off >>= 1) {
            s += __shfl_down_sync(0xffffffff, s, off);
            c += __shfl_down_sync(0xffffffff, c, off);
        }
        if (lane == 0) { ss[warp] = s; cc[warp] = c; }
    }
    __syncthreads();

    if (tid == 0) {
        double acc = 0.0;
        #pragma unroll
        for (int m = 0; m < K; m++) {
            double S   = ss[m] - ((m + 1 < K) ? ss[m + 1] : 0.0);  // bin 5+m loss sum
            double cnt = cc[m] - ((m + 1 < K) ? cc[m + 1] : 0.0);  // bin 5+m count
            double tot = cnt < 1.0 ? 1.0 : cnt;                    // clamp(min=1)
            acc += pow(tot, -0.75) * S;                            // w = tot^-alpha
        }
        out[0] = (float)(acc / (double)n);
        g_ticket = 0;                                               // graph-replay safe
    }
}

extern "C" void kernel_launch(void* const* d_in, const int* in_sizes, int n_in,
                              void* d_out, int out_size) {
    const float* o1 = (const float*)d_in[0];
    const float* o2 = (const float*)d_in[1];
    const float* tg = (const float*)d_in[2];
    float* out = (float*)d_out;
    int n = in_sizes[0];

    ghm_fused_k<<<NB, NT>>>(o1, o2, tg, out, n);
}

// round 6
// speedup vs baseline: 1.4487x; 1.0331x over previous
#include <cuda_runtime.h>
#include <cstdint>

// GHMRankingLoss, fused single kernel, TMA-fed.
//
//   result = (1/N) * sum_{b=5..9} max(cnt_b,1)^-0.75 * S_b
// (bins 0-4 have loss==0). With u = -t*diff and x = u*(2-t), bin 5+m passes
// thresholds T_0..T_m, T = {0, ln(6/4), ln(7/3), ln(8/2), ln(9/1)}.
// Register tallies C_k = sum_{x>=T_k} u, N_k = #{x>=T_k}; difference at the end.
//
// Data movement: cp.async.bulk (1D TMA) streams A/B/T tiles into a 3-stage
// smem ring; mbarrier-paced. No per-warp LDG latency exposure in the hot path;
// consumers read conflict-free LDS.128. Last block (threadfence+ticket)
// reduces partials in double and writes the scalar mean.

#define NT 256
#define NB 592            // 4 CTAs/SM * 148 SMs
#define K 5
#define TILE 1024         // floats per array per stage
#define TBYTES 4096       // TILE * 4
#define STAGES 3

__device__ float2 g_part[K * NB];   // k-major: [k][block] = (C_k, N_k)
__device__ unsigned int g_ticket;   // zero at load; last block resets

struct __align__(128) SmemLayout {
    float a[STAGES][TILE];
    float b[STAGES][TILE];
    float t[STAGES][TILE];
    unsigned long long mbar[STAGES];
};

__device__ __forceinline__ uint32_t smem_u32(const void* p) {
    return (uint32_t)__cvta_generic_to_shared(p);
}
__device__ __forceinline__ void bulk_ld(uint32_t dst, const float* src, uint32_t mbar) {
    asm volatile(
        "cp.async.bulk.shared::cta.global.mbarrier::complete_tx::bytes [%0], [%1], %2, [%3];"
        :: "r"(dst), "l"(src), "n"(TBYTES), "r"(mbar) : "memory");
}
__device__ __forceinline__ void mbar_init(uint32_t mbar, uint32_t cnt) {
    asm volatile("mbarrier.init.shared.b64 [%0], %1;" :: "r"(mbar), "r"(cnt) : "memory");
}
__device__ __forceinline__ void mbar_expect(uint32_t mbar, uint32_t bytes) {
    asm volatile("mbarrier.arrive.expect_tx.shared.b64 _, [%0], %1;"
                 :: "r"(mbar), "r"(bytes) : "memory");
}
__device__ __forceinline__ void mbar_wait(uint32_t mbar, uint32_t parity) {
    asm volatile(
        "{\n\t"
        ".reg .pred P;\n\t"
        "WAIT_%=: mbarrier.try_wait.parity.acquire.cta.shared::cta.b64 P, [%0], %1, 0x989680;\n\t"
        "@P bra.uni DONE_%=;\n\t"
        "bra.uni WAIT_%=;\n\t"
        "DONE_%=:\n\t"
        "}"
        :: "r"(mbar), "r"(parity) : "memory");
}

__device__ __forceinline__ void ghm_accum(
    float& c0, float& c1, float& c2, float& c3, float& c4,
    int& n0, int& n1, int& n2, int& n3, int& n4,
    float a, float b, float t) {
    float diff = a - b;
    float u = -t * diff;            // == loss whenever u >= 0
    float x = u * (2.0f - t);       // sigmoid argument (t=+1 -> u, t=-1 -> 3u)
    bool p0 = (x >= 0.0f);
    bool p1 = (x >= 0.40546511f);   // ln(6/4)
    bool p2 = (x >= 0.84729786f);   // ln(7/3)
    bool p3 = (x >= 1.38629436f);   // ln(8/2)
    bool p4 = (x >= 2.19722458f);   // ln(9/1)
    c0 += p0 ? u : 0.0f;  n0 += p0;
    c1 += p1 ? u : 0.0f;  n1 += p1;
    c2 += p2 ? u : 0.0f;  n2 += p2;
    c3 += p3 ? u : 0.0f;  n3 += p3;
    c4 += p4 ? u : 0.0f;  n4 += p4;
}
#define ACC(av, bv, tv) ghm_accum(c0,c1,c2,c3,c4,n0,n1,n2,n3,n4, av, bv, tv)

__global__ void __launch_bounds__(NT)
ghm_fused_k(const float* __restrict__ o1,
            const float* __restrict__ o2,
            const float* __restrict__ tg,
            float* __restrict__ out,
            int n) {
    __shared__ SmemLayout sm;
    const int tid = threadIdx.x;
    const int bid = blockIdx.x;

    uint32_t mb[STAGES];
    #pragma unroll
    for (int s = 0; s < STAGES; s++) mb[s] = smem_u32(&sm.mbar[s]);

    if (tid == 0) {
        #pragma unroll
        for (int s = 0; s < STAGES; s++) mbar_init(mb[s], 1);
    }
    __syncthreads();

    const int ntiles = n / TILE;                       // full tiles chip-wide
    const int nmine  = (ntiles > bid) ? (ntiles - bid + NB - 1) / NB : 0;

    // prologue: fill the ring
    if (tid == 0) {
        int npre = nmine < STAGES ? nmine : STAGES;
        for (int s = 0; s < npre; s++) {
            int tile = bid + s * NB;
            mbar_expect(mb[s], 3 * TBYTES);
            bulk_ld(smem_u32(&sm.a[s][0]), o1 + (size_t)tile * TILE, mb[s]);
            bulk_ld(smem_u32(&sm.b[s][0]), o2 + (size_t)tile * TILE, mb[s]);
            bulk_ld(smem_u32(&sm.t[s][0]), tg + (size_t)tile * TILE, mb[s]);
        }
    }

    float c0 = 0.f, c1 = 0.f, c2 = 0.f, c3 = 0.f, c4 = 0.f;
    int   n0 = 0,   n1 = 0,   n2 = 0,   n3 = 0,   n4 = 0;

    int slot = 0, parity = 0;
    for (int k = 0; k < nmine; k++) {
        mbar_wait(mb[slot], parity);

        // one float4 per array per thread; conflict-free LDS.128
        float4 av = *(const float4*)&sm.a[slot][tid * 4];
        float4 bv = *(const float4*)&sm.b[slot][tid * 4];
        float4 tv = *(const float4*)&sm.t[slot][tid * 4];
        ACC(av.x, bv.x, tv.x);
        ACC(av.y, bv.y, tv.y);
        ACC(av.z, bv.z, tv.z);
        ACC(av.w, bv.w, tv.w);

        __syncthreads();   // everyone done reading this slot

        if (tid == 0 && k + STAGES < nmine) {
            int tile = bid + (k + STAGES) * NB;
            mbar_expect(mb[slot], 3 * TBYTES);
            bulk_ld(smem_u32(&sm.a[slot][0]), o1 + (size_t)tile * TILE, mb[slot]);
            bulk_ld(smem_u32(&sm.b[slot][0]), o2 + (size_t)tile * TILE, mb[slot]);
            bulk_ld(smem_u32(&sm.t[slot][0]), tg + (size_t)tile * TILE, mb[slot]);
        }

        if (++slot == STAGES) { slot = 0; parity ^= 1; }
    }

    // tail (n not a multiple of TILE): block 0 handles it with plain LDGs
    if (bid == 0) {
        for (int j = ntiles * TILE + tid; j < n; j += NT)
            ACC(o1[j], o2[j], tg[j]);
    }

    // ---- block reduce: warp shfl, then cross-warp via smem ----
    float cs[K] = {c0, c1, c2, c3, c4};
    float ns[K] = {(float)n0, (float)n1, (float)n2, (float)n3, (float)n4};
    #pragma unroll
    for (int off = 16; off; off >>= 1) {
        #pragma unroll
        for (int k = 0; k < K; k++) {
            cs[k] += __shfl_down_sync(0xffffffff, cs[k], off);
            ns[k] += __shfl_down_sync(0xffffffff, ns[k], off);
        }
    }

    __shared__ float sC[K][NT / 32], sN[K][NT / 32];
    const int warp = tid >> 5, lane = tid & 31;
    if (lane == 0) {
        #pragma unroll
        for (int k = 0; k < K; k++) { sC[k][warp] = cs[k]; sN[k][warp] = ns[k]; }
    }
    __syncthreads();

    if (tid < K) {
        float c = 0.f, nn = 0.f;
        #pragma unroll
        for (int w = 0; w < NT / 32; w++) { c += sC[tid][w]; nn += sN[tid][w]; }
        g_part[tid * NB + bid] = make_float2(c, nn);
    }

    // ---- ticket: last block finalizes ----
    __shared__ bool isLast;
    __threadfence();
    if (tid == 0) {
        unsigned int v = atomicAdd(&g_ticket, 1u);
        isLast = (v == NB - 1);
    }
    __syncthreads();
    if (!isLast) return;

    __shared__ double ss[K], cc[K];
    if (warp < K) {
        double s = 0.0, c = 0.0;
        for (int j = lane; j < NB; j += 32) {
            float2 p = g_part[warp * NB + j];   // L2-resident
            s += (double)p.x;
            c += (double)p.y;
        }
        #pragma unroll
        for (int off = 16; off; off >>= 1) {
            s += __shfl_down_sync(0xffffffff, s, off);
            c += __shfl_down_sync(0xffffffff, c, off);
        }
        if (lane == 0) { ss[warp] = s; cc[warp] = c; }
    }
    __syncthreads();

    if (tid == 0) {
        double acc = 0.0;
        #pragma unroll
        for (int m = 0; m < K; m++) {
            double S   = ss[m] - ((m + 1 < K) ? ss[m + 1] : 0.0);  // bin 5+m loss sum
            double cnt = cc[m] - ((m + 1 < K) ? cc[m + 1] : 0.0);  // bin 5+m count
            double tot = cnt < 1.0 ? 1.0 : cnt;                    // clamp(min=1)
            acc += pow(tot, -0.75) * S;                            // w = tot^-alpha
        }
        out[0] = (float)(acc / (double)n);
        g_ticket = 0;                                               // graph-replay safe
    }
}

extern "C" void kernel_launch(void* const* d_in, const int* in_sizes, int n_in,
                              void* d_out, int out_size) {
    const float* o1 = (const float*)d_in[0];
    const float* o2 = (const float*)d_in[1];
    const float* tg = (const float*)d_in[2];
    float* out = (float*)d_out;
    int n = in_sizes[0];

    ghm_fused_k<<<NB, NT>>>(o1, o2, tg, out, n);
}

// round 7
// speedup vs baseline: 1.5125x; 1.0441x over previous
#include <cuda_runtime.h>

// GHMRankingLoss, fused single kernel, minimal-instruction hot loop.
//
//   result = (1/N) * sum_{b=5..9} max(cnt_b,1)^-0.75 * S_b
// (bins 0-4 have loss==0). With u = -t*diff and x = u*(2-t), bin 5+m passes
// thresholds T_0..T_m, T = {0, ln(6/4), ln(7/3), ln(8/2), ln(9/1)}.
// Cumulative tallies C_k = sum_{x>=T_k} u, N_k = #{x>=T_k}; differenced at end.
//
// Hot loop codegen: set.ge.f32 -> FSET gives r in {0.0f, 1.0f} in ONE SASS op;
// then C_k via a single FFMA(r,u,C_k) (exact: r is 0 or 1) and N_k via one
// FADD. 3 instructions per threshold, no FSEL/branch/predicate chains.
// Plain LDG.128 streaming, unroll-2 front-batched, 6 CTAs/SM.

#define NT 256
#define NB 888    // 6 CTAs/SM * 148 SMs
#define K  5

__device__ float2 g_part[K * NB];   // k-major: [k][block] = (C_k, N_k)
__device__ unsigned int g_ticket;   // zero at load; last block resets

__device__ __forceinline__ float fset_ge(float x, float T) {
    float r;
    asm("set.ge.f32.f32 %0, %1, %2;" : "=f"(r) : "f"(x), "f"(T));
    return r;   // 1.0f if x >= T else 0.0f
}

__device__ __forceinline__ void ghm_accum(
    float& c0, float& c1, float& c2, float& c3, float& c4,
    float& n0, float& n1, float& n2, float& n3, float& n4,
    float a, float b, float t) {
    float diff = a - b;
    float u = -t * diff;            // == loss whenever u >= 0
    float x = u * (2.0f - t);       // sigmoid argument (t=+1 -> u, t=-1 -> 3u)
    float r0 = fset_ge(x, 0.0f);
    float r1 = fset_ge(x, 0.40546511f);   // ln(6/4)
    float r2 = fset_ge(x, 0.84729786f);   // ln(7/3)
    float r3 = fset_ge(x, 1.38629436f);   // ln(8/2)
    float r4 = fset_ge(x, 2.19722458f);   // ln(9/1)
    c0 = fmaf(r0, u, c0);  n0 += r0;
    c1 = fmaf(r1, u, c1);  n1 += r1;
    c2 = fmaf(r2, u, c2);  n2 += r2;
    c3 = fmaf(r3, u, c3);  n3 += r3;
    c4 = fmaf(r4, u, c4);  n4 += r4;
}
#define ACC(av, bv, tv) ghm_accum(c0,c1,c2,c3,c4,n0,n1,n2,n3,n4, av, bv, tv)

__global__ void __launch_bounds__(NT, 6)
ghm_fused_k(const float* __restrict__ o1,
            const float* __restrict__ o2,
            const float* __restrict__ tg,
            float* __restrict__ out,
            int n) {
    const int tid = threadIdx.x;
    const int bid = blockIdx.x;

    float c0 = 0.f, c1 = 0.f, c2 = 0.f, c3 = 0.f, c4 = 0.f;
    float n0 = 0.f, n1 = 0.f, n2 = 0.f, n3 = 0.f, n4 = 0.f;

    const int n4e    = n >> 2;
    const int stride = NB * NT;
    int i = bid * NT + tid;

    const float4* __restrict__ A = (const float4*)o1;
    const float4* __restrict__ B = (const float4*)o2;
    const float4* __restrict__ T = (const float4*)tg;

    // unroll-2: 6 front-batched LDG.128 per iteration for MLP
    for (; i + stride < n4e; i += 2 * stride) {
        float4 a0 = __ldcs(A + i);
        float4 b0 = __ldcs(B + i);
        float4 t0 = __ldcs(T + i);
        float4 a1 = __ldcs(A + i + stride);
        float4 b1 = __ldcs(B + i + stride);
        float4 t1 = __ldcs(T + i + stride);
        ACC(a0.x, b0.x, t0.x);  ACC(a0.y, b0.y, t0.y);
        ACC(a0.z, b0.z, t0.z);  ACC(a0.w, b0.w, t0.w);
        ACC(a1.x, b1.x, t1.x);  ACC(a1.y, b1.y, t1.y);
        ACC(a1.z, b1.z, t1.z);  ACC(a1.w, b1.w, t1.w);
    }
    for (; i < n4e; i += stride) {
        float4 a = __ldcs(A + i);
        float4 b = __ldcs(B + i);
        float4 t = __ldcs(T + i);
        ACC(a.x, b.x, t.x);  ACC(a.y, b.y, t.y);
        ACC(a.z, b.z, t.z);  ACC(a.w, b.w, t.w);
    }
    for (int j = (n4e << 2) + bid * NT + tid; j < n; j += stride)
        ACC(o1[j], o2[j], tg[j]);

    // ---- block reduce: warp shfl, then cross-warp via smem ----
    float cs[K] = {c0, c1, c2, c3, c4};
    float ns[K] = {n0, n1, n2, n3, n4};
    #pragma unroll
    for (int off = 16; off; off >>= 1) {
        #pragma unroll
        for (int k = 0; k < K; k++) {
            cs[k] += __shfl_down_sync(0xffffffff, cs[k], off);
            ns[k] += __shfl_down_sync(0xffffffff, ns[k], off);
        }
    }

    __shared__ float sC[K][NT / 32], sN[K][NT / 32];
    const int warp = tid >> 5, lane = tid & 31;
    if (lane == 0) {
        #pragma unroll
        for (int k = 0; k < K; k++) { sC[k][warp] = cs[k]; sN[k][warp] = ns[k]; }
    }
    __syncthreads();

    if (tid < K) {
        float c = 0.f, nn = 0.f;
        #pragma unroll
        for (int w = 0; w < NT / 32; w++) { c += sC[tid][w]; nn += sN[tid][w]; }
        g_part[tid * NB + bid] = make_float2(c, nn);
    }

    // ---- ticket: last block finalizes ----
    __shared__ bool isLast;
    __threadfence();
    if (tid == 0) {
        unsigned int v = atomicAdd(&g_ticket, 1u);
        isLast = (v == NB - 1);
    }
    __syncthreads();
    if (!isLast) return;

    __shared__ double ss[K], cc[K];
    if (warp < K) {
        double s = 0.0, c = 0.0;
        for (int j = lane; j < NB; j += 32) {
            float2 p = g_part[warp * NB + j];   // L2-resident
            s += (double)p.x;
            c += (double)p.y;
        }
        #pragma unroll
        for (int off = 16; off; off >>= 1) {
            s += __shfl_down_sync(0xffffffff, s, off);
            c += __shfl_down_sync(0xffffffff, c, off);
        }
        if (lane == 0) { ss[warp] = s; cc[warp] = c; }
    }
    __syncthreads();

    if (tid == 0) {
        double acc = 0.0;
        #pragma unroll
        for (int m = 0; m < K; m++) {
            double S   = ss[m] - ((m + 1 < K) ? ss[m + 1] : 0.0);  // bin 5+m loss sum
            double cnt = cc[m] - ((m + 1 < K) ? cc[m + 1] : 0.0);  // bin 5+m count
            double tot = cnt < 1.0 ? 1.0 : cnt;                    // clamp(min=1)
            acc += pow(tot, -0.75) * S;                            // w = tot^-alpha
        }
        out[0] = (float)(acc / (double)n);
        g_ticket = 0;                                               // graph-replay safe
    }
}

extern "C" void kernel_launch(void* const* d_in, const int* in_sizes, int n_in,
                              void* d_out, int out_size) {
    const float* o1 = (const float*)d_in[0];
    const float* o2 = (const float*)d_in[1];
    const float* tg = (const float*)d_in[2];
    float* out = (float*)d_out;
    int n = in_sizes[0];

    ghm_fused_k<<<NB, NT>>>(o1, o2, tg, out, n);
}